// round 11
// baseline (speedup 1.0000x reference)
#include <cuda_runtime.h>
#include <cuda_bf16.h>
#include <cstdint>

// CrossAttention: out = softmax((x Wq)(ctx Wk)^T * DIM^-0.5) (ctx Wv) + x
// Pipeline: Q proj (*scale) ; fused K|V proj (N=1024) ; V^T ; S GEMM with
// exp epilogue + row-sum atomics ; PV GEMM with 1/l + residual.
// GEMM warp tile 64x64 (4m x 2n warps) to cut LDSM traffic per FLOP.

#define BATCH 4
#define SEQ   4096
#define DIM   512
#define CTXD  768

typedef __nv_bfloat16 bf16;

// ---------------- scratch ----------------------------------------------------
__device__ bf16  g_Xb [(size_t)BATCH * SEQ * DIM];
__device__ bf16  g_Cb [(size_t)BATCH * SEQ * CTXD];
__device__ bf16  g_WqT[(size_t)DIM * DIM];
__device__ bf16  g_Wkv[(size_t)1024 * CTXD];            // [Wk^T ; Wv^T]
__device__ bf16  g_Qb [(size_t)BATCH * SEQ * DIM];      // pre-scaled
__device__ bf16  g_KV [(size_t)BATCH * SEQ * 1024];     // K | V per row
__device__ bf16  g_VT [(size_t)BATCH * DIM * SEQ];
__device__ bf16  g_P  [(size_t)BATCH * SEQ * SEQ];      // exp(S)
__device__ float g_L  [(size_t)BATCH * SEQ];            // row sums

// ---------------- PTX helpers ------------------------------------------------
__device__ __forceinline__ uint32_t smem_u32(const void* p) {
    uint32_t a;
    asm("{ .reg .u64 t; cvta.to.shared.u64 t, %1; cvt.u32.u64 %0, t; }"
        : "=r"(a) : "l"(p));
    return a;
}
#define CP_ASYNC16(dst, src) \
    asm volatile("cp.async.cg.shared.global [%0], [%1], 16;" :: "r"(dst), "l"(src))
#define CP_COMMIT() asm volatile("cp.async.commit_group;" ::: "memory")
#define CP_WAIT(n)  asm volatile("cp.async.wait_group %0;" :: "n"(n) : "memory")

#define LDSM4(r0, r1, r2, r3, addr) \
    asm volatile("ldmatrix.sync.aligned.m8n8.x4.shared.b16 {%0,%1,%2,%3}, [%4];" \
        : "=r"(r0), "=r"(r1), "=r"(r2), "=r"(r3) : "r"(addr))

#define MMA16816(d, a, b) \
    asm volatile("mma.sync.aligned.m16n8k16.row.col.f32.bf16.bf16.f32 " \
        "{%0,%1,%2,%3}, {%4,%5,%6,%7}, {%8,%9}, {%0,%1,%2,%3};" \
        : "+f"((d)[0]), "+f"((d)[1]), "+f"((d)[2]), "+f"((d)[3]) \
        : "r"((a)[0]), "r"((a)[1]), "r"((a)[2]), "r"((a)[3]), \
          "r"((b)[0]), "r"((b)[1]))

__device__ __forceinline__ uint32_t pk2(float lo, float hi) {
    __nv_bfloat162 h = __floats2bfloat162_rn(lo, hi);
    return *reinterpret_cast<uint32_t*>(&h);
}

// ---------------- bf16 mma GEMM: D = A(M,K) * B(N,K)^T ----------------------
// CTA 256x128, BK=64, 3-stage cp.async, 8 warps (4m x 2n), warp tile 64x64.
// ldA/ldB are row strides in elems (k-advance is contiguous within rows).
// MODE 0: bf16 out * alpha
// MODE 3: bf16 out = exp(acc); atomicAdd row-sums into L
// MODE 4: f32 out = acc / L[row] + residual R
#define STAGES 3
#define A_BYTES 32768
#define B_BYTES 16384
#define STAGE_BYTES (A_BYTES + B_BYTES)
#define GEMM_SMEM (STAGES * STAGE_BYTES + 128)

__device__ __forceinline__ void tile_async_A(const bf16* g, int ld, uint32_t stg, int tid) {
#pragma unroll
    for (int t = 0; t < 8; t++) {
        const int f = tid + t * 256, row = f >> 3, seg = f & 7;
        CP_ASYNC16(stg + row * 128 + ((seg ^ (row & 7)) << 4),
                   (const char*)g + (long)row * ld * 2 + seg * 16);
    }
}
__device__ __forceinline__ void tile_async_B(const bf16* g, int ld, uint32_t stg, int tid) {
#pragma unroll
    for (int t = 0; t < 4; t++) {
        const int f = tid + t * 256, row = f >> 3, seg = f & 7;
        CP_ASYNC16(stg + row * 128 + ((seg ^ (row & 7)) << 4),
                   (const char*)g + (long)row * ld * 2 + seg * 16);
    }
}

template <int MODE>
__global__ __launch_bounds__(256)
void gemm_mma(const bf16* __restrict__ A, const bf16* __restrict__ B,
              void* __restrict__ Cv, const float* __restrict__ R,
              float* __restrict__ L,
              int Ncols, int Kd, int ldA, int ldB,
              long sA, long sB, long sC, float alpha)
{
    extern __shared__ char smraw[];
    const uint32_t smbase = (smem_u32(smraw) + 127u) & ~127u;

    const int tid = threadIdx.x, lane = tid & 31, wid = tid >> 5;
    const int wm = wid >> 1, wn = wid & 1;     // 4 x 2 warps, 64x64 tiles
    const int bz = blockIdx.z;
    const long bm = (long)blockIdx.y * 256;
    const long bn = (long)blockIdx.x * 128;

    A += bz * sA + bm * ldA;
    B += bz * sB + bn * ldB;

    const int g = lane >> 3, lr = lane & 7;
    const int arow0 = wm * 64 + (g & 1) * 8 + lr, aseg0 = g >> 1, axor = arow0 & 7;
    const int brow0 = wn * 64 + (g >> 1) * 8 + lr, bseg0 = g & 1, bxor = brow0 & 7;

    float acc[4][8][4];
#pragma unroll
    for (int i = 0; i < 4; i++)
#pragma unroll
        for (int j = 0; j < 8; j++)
#pragma unroll
            for (int q = 0; q < 4; q++) acc[i][j][q] = 0.0f;

    const int NC = Kd >> 6;
#pragma unroll
    for (int c = 0; c < 2; c++) {
        const uint32_t stg = smbase + c * STAGE_BYTES;
        tile_async_A(A + c * 64, ldA, stg, tid);
        tile_async_B(B + c * 64, ldB, stg + A_BYTES, tid);
        CP_COMMIT();
    }

    for (int c = 0; c < NC; c++) {
        if (c == NC - 1) { CP_WAIT(0); } else { CP_WAIT(1); }
        __syncthreads();
        if (c + 2 < NC) {
            const uint32_t stg = smbase + ((c + 2) % STAGES) * STAGE_BYTES;
            tile_async_A(A + (c + 2) * 64, ldA, stg, tid);
            tile_async_B(B + (c + 2) * 64, ldB, stg + A_BYTES, tid);
            CP_COMMIT();
        }
        const uint32_t sa = smbase + (c % STAGES) * STAGE_BYTES;
        const uint32_t sb = sa + A_BYTES;
#pragma unroll
        for (int ks = 0; ks < 4; ks++) {
            uint32_t af[4][4];
#pragma unroll
            for (int i = 0; i < 4; i++)
                LDSM4(af[i][0], af[i][1], af[i][2], af[i][3],
                      sa + (arow0 + i * 16) * 128 + ((((ks << 1) + aseg0) ^ axor) << 4));
            uint32_t bfr[8][2];
#pragma unroll
            for (int jp = 0; jp < 4; jp++) {
                uint32_t r0, r1, r2, r3;
                LDSM4(r0, r1, r2, r3,
                      sb + (brow0 + jp * 16) * 128 + ((((ks << 1) + bseg0) ^ bxor) << 4));
                bfr[2 * jp][0] = r0; bfr[2 * jp][1] = r1;
                bfr[2 * jp + 1][0] = r2; bfr[2 * jp + 1][1] = r3;
            }
#pragma unroll
            for (int i = 0; i < 4; i++)
#pragma unroll
                for (int j = 0; j < 8; j++)
                    MMA16816(acc[i][j], af[i], bfr[j]);
        }
    }

    // ---------------- epilogue ----------------
    const int r = lane >> 2, c2 = (lane & 3) * 2;
#pragma unroll
    for (int i = 0; i < 4; i++) {
        const long row0 = bm + wm * 64 + i * 16 + r;        // per-batch row
        const long rowb = row0 + 8;
        float il0 = 1.0f, il1 = 1.0f;
        if (MODE == 4) {
            il0 = 1.0f / __ldg(L + (long)bz * SEQ + row0);
            il1 = 1.0f / __ldg(L + (long)bz * SEQ + rowb);
        }
        float slo = 0.0f, shi = 0.0f;
#pragma unroll
        for (int j = 0; j < 8; j++) {
            const int  col = bn + wn * 64 + j * 8 + c2;
            const long o0 = row0 * (long)Ncols + col + bz * sC;
            const long o1 = rowb * (long)Ncols + col + bz * sC;
            if (MODE == 0) {
                *(uint32_t*)((bf16*)Cv + o0) = pk2(acc[i][j][0] * alpha, acc[i][j][1] * alpha);
                *(uint32_t*)((bf16*)Cv + o1) = pk2(acc[i][j][2] * alpha, acc[i][j][3] * alpha);
            } else if (MODE == 3) {
                const float e0 = __expf(acc[i][j][0]);
                const float e1 = __expf(acc[i][j][1]);
                const float e2 = __expf(acc[i][j][2]);
                const float e3 = __expf(acc[i][j][3]);
                slo += e0 + e1; shi += e2 + e3;
                *(uint32_t*)((bf16*)Cv + o0) = pk2(e0, e1);
                *(uint32_t*)((bf16*)Cv + o1) = pk2(e2, e3);
            } else {  // MODE 4
                const float2 r0 = *(const float2*)(R + o0);
                const float2 r1 = *(const float2*)(R + o1);
                *(float2*)((float*)Cv + o0) =
                    make_float2(acc[i][j][0] * il0 + r0.x, acc[i][j][1] * il0 + r0.y);
                *(float2*)((float*)Cv + o1) =
                    make_float2(acc[i][j][2] * il1 + r1.x, acc[i][j][3] * il1 + r1.y);
            }
        }
        if (MODE == 3) {
            slo += __shfl_xor_sync(0xFFFFFFFFu, slo, 1);
            slo += __shfl_xor_sync(0xFFFFFFFFu, slo, 2);
            shi += __shfl_xor_sync(0xFFFFFFFFu, shi, 1);
            shi += __shfl_xor_sync(0xFFFFFFFFu, shi, 2);
            if ((lane & 3) == 0) {
                atomicAdd(L + (long)bz * SEQ + row0, slo);
                atomicAdd(L + (long)bz * SEQ + rowb, shi);
            }
        }
    }
}

// ---------------- helper kernels ---------------------------------------------
__global__ __launch_bounds__(256)
void zero_l(float* __restrict__ L) {
    L[blockIdx.x * 256 + threadIdx.x] = 0.0f;
}

__global__ __launch_bounds__(256)
void cvt_bf16(const float* __restrict__ in, bf16* __restrict__ out) {
    const long i = (long)blockIdx.x * 256 + threadIdx.x;
    const float4* p = (const float4*)in + i * 2;
    const float4 a = p[0], b = p[1];
    ((uint4*)out)[i] = make_uint4(pk2(a.x, a.y), pk2(a.z, a.w),
                                  pk2(b.x, b.y), pk2(b.z, b.w));
}

__global__ __launch_bounds__(256)
void wtransb(const float* __restrict__ W, bf16* __restrict__ WT, int Kin, int Nout) {
    __shared__ float t[32][33];
    const int n0 = blockIdx.x * 32, k0 = blockIdx.y * 32;
    const int tx = threadIdx.x & 31, ty = threadIdx.x >> 5;
#pragma unroll
    for (int i = 0; i < 4; i++)
        t[ty + 8 * i][tx] = W[(long)(k0 + ty + 8 * i) * Nout + n0 + tx];
    __syncthreads();
#pragma unroll
    for (int i = 0; i < 4; i++)
        WT[(long)(n0 + ty + 8 * i) * Kin + k0 + tx] = __float2bfloat16(t[tx][ty + 8 * i]);
}

// V half of KV (row stride srcStride elems) -> VT [DIM x SEQ] per batch
__global__ __launch_bounds__(256)
void vtransb(const bf16* __restrict__ V, bf16* __restrict__ VT, int srcStride) {
    __shared__ bf16 t[32][33];
    const long bi = (long)blockIdx.z * SEQ * srcStride;
    const long bo = (long)blockIdx.z * DIM * SEQ;
    const int d0 = blockIdx.x * 32, m0 = blockIdx.y * 32;
    const int tx = threadIdx.x & 31, ty = threadIdx.x >> 5;
#pragma unroll
    for (int i = 0; i < 4; i++)
        t[ty + 8 * i][tx] = V[bi + (long)(m0 + ty + 8 * i) * srcStride + d0 + tx];
    __syncthreads();
#pragma unroll
    for (int i = 0; i < 4; i++)
        VT[bo + (long)(d0 + ty + 8 * i) * SEQ + m0 + tx] = t[tx][ty + 8 * i];
}

// ---------------- launcher ---------------------------------------------------
extern "C" void kernel_launch(void* const* d_in, const int* in_sizes, int n_in,
                              void* d_out, int out_size)
{
    const float* x   = (const float*)d_in[0];
    const float* ctx = (const float*)d_in[1];
    const float* Wq  = (const float*)d_in[2];
    const float* Wk  = (const float*)d_in[3];
    const float* Wv  = (const float*)d_in[4];
    float* out = (float*)d_out;

    bf16 *Xb, *Cb, *WqT, *Wkv, *Qb, *KV, *VT, *P;
    float* L;
    cudaGetSymbolAddress((void**)&Xb,  g_Xb);
    cudaGetSymbolAddress((void**)&Cb,  g_Cb);
    cudaGetSymbolAddress((void**)&WqT, g_WqT);
    cudaGetSymbolAddress((void**)&Wkv, g_Wkv);
    cudaGetSymbolAddress((void**)&Qb,  g_Qb);
    cudaGetSymbolAddress((void**)&KV,  g_KV);
    cudaGetSymbolAddress((void**)&VT,  g_VT);
    cudaGetSymbolAddress((void**)&P,   g_P);
    cudaGetSymbolAddress((void**)&L,   g_L);

    cudaFuncSetAttribute(gemm_mma<0>, cudaFuncAttributeMaxDynamicSharedMemorySize, GEMM_SMEM);
    cudaFuncSetAttribute(gemm_mma<3>, cudaFuncAttributeMaxDynamicSharedMemorySize, GEMM_SMEM);
    cudaFuncSetAttribute(gemm_mma<4>, cudaFuncAttributeMaxDynamicSharedMemorySize, GEMM_SMEM);

    const float scale = 0.044194173824159216f;  // 512^-0.5

    zero_l<<<(BATCH * SEQ) / 256, 256>>>(L);

    cvt_bf16<<<(BATCH * SEQ * DIM)  / (256 * 8), 256>>>(x,   Xb);
    cvt_bf16<<<(BATCH * SEQ * CTXD) / (256 * 8), 256>>>(ctx, Cb);

    wtransb<<<dim3(DIM / 32, DIM  / 32), 256>>>(Wq, WqT, DIM,  DIM);
    wtransb<<<dim3(DIM / 32, CTXD / 32), 256>>>(Wk, Wkv,              CTXD, DIM);
    wtransb<<<dim3(DIM / 32, CTXD / 32), 256>>>(Wv, Wkv + 512 * CTXD, CTXD, DIM);

    // Q = x Wq * scale   (16384 x 512, K=512)
    gemm_mma<0><<<dim3(DIM / 128, (BATCH * SEQ) / 256, 1), 256, GEMM_SMEM>>>(
        Xb, WqT, Qb, nullptr, nullptr, DIM, DIM, DIM, DIM, 0, 0, 0, scale);
    // KV = ctx [Wk|Wv]   (16384 x 1024, K=768)
    gemm_mma<0><<<dim3(1024 / 128, (BATCH * SEQ) / 256, 1), 256, GEMM_SMEM>>>(
        Cb, Wkv, KV, nullptr, nullptr, 1024, CTXD, CTXD, CTXD, 0, 0, 0, 1.0f);

    // VT per batch from V half of KV
    vtransb<<<dim3(DIM / 32, SEQ / 32, BATCH), 256>>>(KV + 512, VT, 1024);

    // P = exp(Q K^T), L = row sums (softmax fused into epilogue)
    gemm_mma<3><<<dim3(SEQ / 128, SEQ / 256, BATCH), 256, GEMM_SMEM>>>(
        Qb, KV, P, nullptr, L, SEQ, DIM, DIM, 1024,
        (long)SEQ * DIM, (long)SEQ * 1024, (long)SEQ * SEQ, 1.0f);

    // out = (P V) / l + x
    gemm_mma<4><<<dim3(DIM / 128, SEQ / 256, BATCH), 256, GEMM_SMEM>>>(
        P, VT, out, x, L, DIM, SEQ, SEQ, SEQ,
        (long)SEQ * SEQ, (long)DIM * SEQ, (long)SEQ * DIM, 1.0f);
}

// round 13
// speedup vs baseline: 1.0648x; 1.0648x over previous
#include <cuda_runtime.h>
#include <cuda_bf16.h>
#include <cstdint>

// CrossAttention: out = softmax((x Wq)(ctx Wk)^T * DIM^-0.5) (ctx Wv) + x
// R10 pipeline (606us) with helper launches merged:
//   prep_all (cvt x | cvt ctx | zero L) ; wtrans3 (Wq|Wk|Wv) ;
//   proj Q(*scale)/K/V ; V^T ; S GEMM + exp epilogue + row-sum atomics ;
//   PV GEMM with 1/l + residual.

#define BATCH 4
#define SEQ   4096
#define DIM   512
#define CTXD  768

typedef __nv_bfloat16 bf16;

// ---------------- scratch ----------------------------------------------------
__device__ bf16  g_Xb [(size_t)BATCH * SEQ * DIM];
__device__ bf16  g_Cb [(size_t)BATCH * SEQ * CTXD];
__device__ bf16  g_WqT[(size_t)DIM * DIM];
__device__ bf16  g_WkT[(size_t)DIM * CTXD];
__device__ bf16  g_WvT[(size_t)DIM * CTXD];
__device__ bf16  g_Qb [(size_t)BATCH * SEQ * DIM];      // pre-scaled
__device__ bf16  g_Kb [(size_t)BATCH * SEQ * DIM];
__device__ bf16  g_Vb [(size_t)BATCH * SEQ * DIM];
__device__ bf16  g_VT [(size_t)BATCH * DIM * SEQ];
__device__ bf16  g_P  [(size_t)BATCH * SEQ * SEQ];      // exp(S)
__device__ float g_L  [(size_t)BATCH * SEQ];            // row sums

// ---------------- PTX helpers ------------------------------------------------
__device__ __forceinline__ uint32_t smem_u32(const void* p) {
    uint32_t a;
    asm("{ .reg .u64 t; cvta.to.shared.u64 t, %1; cvt.u32.u64 %0, t; }"
        : "=r"(a) : "l"(p));
    return a;
}
#define CP_ASYNC16(dst, src) \
    asm volatile("cp.async.cg.shared.global [%0], [%1], 16;" :: "r"(dst), "l"(src))
#define CP_COMMIT() asm volatile("cp.async.commit_group;" ::: "memory")
#define CP_WAIT(n)  asm volatile("cp.async.wait_group %0;" :: "n"(n) : "memory")

#define LDSM4(r0, r1, r2, r3, addr) \
    asm volatile("ldmatrix.sync.aligned.m8n8.x4.shared.b16 {%0,%1,%2,%3}, [%4];" \
        : "=r"(r0), "=r"(r1), "=r"(r2), "=r"(r3) : "r"(addr))

#define MMA16816(d, a, b) \
    asm volatile("mma.sync.aligned.m16n8k16.row.col.f32.bf16.bf16.f32 " \
        "{%0,%1,%2,%3}, {%4,%5,%6,%7}, {%8,%9}, {%0,%1,%2,%3};" \
        : "+f"((d)[0]), "+f"((d)[1]), "+f"((d)[2]), "+f"((d)[3]) \
        : "r"((a)[0]), "r"((a)[1]), "r"((a)[2]), "r"((a)[3]), \
          "r"((b)[0]), "r"((b)[1]))

__device__ __forceinline__ uint32_t pk2(float lo, float hi) {
    __nv_bfloat162 h = __floats2bfloat162_rn(lo, hi);
    return *reinterpret_cast<uint32_t*>(&h);
}

// ---------------- bf16 mma GEMM: D = A(M,K) * B(N,K)^T ----------------------
// CTA 256x128, BK=64, 3-stage cp.async, 8 warps 2x4, warp tile 128x32.
// MODE 0: bf16 out * alpha
// MODE 3: bf16 out = exp(acc); atomicAdd row-sums into L
// MODE 4: f32 out = acc / L[row] + residual R
#define STAGES 3
#define A_BYTES 32768
#define B_BYTES 16384
#define STAGE_BYTES (A_BYTES + B_BYTES)
#define GEMM_SMEM (STAGES * STAGE_BYTES + 128)

__device__ __forceinline__ void tile_async_A(const bf16* g, int ld, uint32_t stg, int tid) {
#pragma unroll
    for (int t = 0; t < 8; t++) {
        const int f = tid + t * 256, row = f >> 3, seg = f & 7;
        CP_ASYNC16(stg + row * 128 + ((seg ^ (row & 7)) << 4),
                   (const char*)g + (long)row * ld * 2 + seg * 16);
    }
}
__device__ __forceinline__ void tile_async_B(const bf16* g, int ld, uint32_t stg, int tid) {
#pragma unroll
    for (int t = 0; t < 4; t++) {
        const int f = tid + t * 256, row = f >> 3, seg = f & 7;
        CP_ASYNC16(stg + row * 128 + ((seg ^ (row & 7)) << 4),
                   (const char*)g + (long)row * ld * 2 + seg * 16);
    }
}

template <int MODE>
__global__ __launch_bounds__(256)
void gemm_mma(const bf16* __restrict__ A, const bf16* __restrict__ B,
              void* __restrict__ Cv, const float* __restrict__ R,
              float* __restrict__ L,
              int Ncols, int Kd, long sA, long sB, long sC, float alpha)
{
    extern __shared__ char smraw[];
    const uint32_t smbase = (smem_u32(smraw) + 127u) & ~127u;

    const int tid = threadIdx.x, lane = tid & 31, wid = tid >> 5;
    const int wm = wid >> 2, wn = wid & 3;
    const int bz = blockIdx.z;
    const long bm = (long)blockIdx.y * 256;
    const long bn = (long)blockIdx.x * 128;

    A += bz * sA + bm * Kd;
    B += bz * sB + bn * Kd;

    const int g = lane >> 3, lr = lane & 7;
    const int arow0 = wm * 128 + (g & 1) * 8 + lr, aseg0 = g >> 1, axor = arow0 & 7;
    const int brow0 = wn * 32 + (g >> 1) * 8 + lr, bseg0 = g & 1, bxor = brow0 & 7;

    float acc[8][4][4];
#pragma unroll
    for (int i = 0; i < 8; i++)
#pragma unroll
        for (int j = 0; j < 4; j++)
#pragma unroll
            for (int q = 0; q < 4; q++) acc[i][j][q] = 0.0f;

    const int NC = Kd >> 6;
#pragma unroll
    for (int c = 0; c < 2; c++) {
        const uint32_t stg = smbase + c * STAGE_BYTES;
        tile_async_A(A + c * 64, Kd, stg, tid);
        tile_async_B(B + c * 64, Kd, stg + A_BYTES, tid);
        CP_COMMIT();
    }

    for (int c = 0; c < NC; c++) {
        if (c == NC - 1) { CP_WAIT(0); } else { CP_WAIT(1); }
        __syncthreads();
        if (c + 2 < NC) {
            const uint32_t stg = smbase + ((c + 2) % STAGES) * STAGE_BYTES;
            tile_async_A(A + (c + 2) * 64, Kd, stg, tid);
            tile_async_B(B + (c + 2) * 64, Kd, stg + A_BYTES, tid);
            CP_COMMIT();
        }
        const uint32_t sa = smbase + (c % STAGES) * STAGE_BYTES;
        const uint32_t sb = sa + A_BYTES;
#pragma unroll
        for (int ks = 0; ks < 4; ks++) {
            uint32_t af[8][4];
#pragma unroll
            for (int i = 0; i < 8; i++)
                LDSM4(af[i][0], af[i][1], af[i][2], af[i][3],
                      sa + (arow0 + i * 16) * 128 + ((((ks << 1) + aseg0) ^ axor) << 4));
            uint32_t bfr[4][2];
#pragma unroll
            for (int jp = 0; jp < 2; jp++) {
                uint32_t r0, r1, r2, r3;
                LDSM4(r0, r1, r2, r3,
                      sb + (brow0 + jp * 16) * 128 + ((((ks << 1) + bseg0) ^ bxor) << 4));
                bfr[2 * jp][0] = r0; bfr[2 * jp][1] = r1;
                bfr[2 * jp + 1][0] = r2; bfr[2 * jp + 1][1] = r3;
            }
#pragma unroll
            for (int i = 0; i < 8; i++)
#pragma unroll
                for (int j = 0; j < 4; j++)
                    MMA16816(acc[i][j], af[i], bfr[j]);
        }
    }

    // ---------------- epilogue ----------------
    const int r = lane >> 2, c2 = (lane & 3) * 2;
#pragma unroll
    for (int i = 0; i < 8; i++) {
        const long row0 = bm + wm * 128 + i * 16 + r;       // per-batch row
        const long rowb = row0 + 8;
        float il0 = 1.0f, il1 = 1.0f;
        if (MODE == 4) {
            il0 = 1.0f / __ldg(L + (long)bz * SEQ + row0);
            il1 = 1.0f / __ldg(L + (long)bz * SEQ + rowb);
        }
        float slo = 0.0f, shi = 0.0f;
#pragma unroll
        for (int j = 0; j < 4; j++) {
            const int  col = bn + wn * 32 + j * 8 + c2;
            const long o0 = row0 * (long)Ncols + col + bz * sC;
            const long o1 = rowb * (long)Ncols + col + bz * sC;
            if (MODE == 0) {
                *(uint32_t*)((bf16*)Cv + o0) = pk2(acc[i][j][0] * alpha, acc[i][j][1] * alpha);
                *(uint32_t*)((bf16*)Cv + o1) = pk2(acc[i][j][2] * alpha, acc[i][j][3] * alpha);
            } else if (MODE == 3) {
                const float e0 = __expf(acc[i][j][0]);
                const float e1 = __expf(acc[i][j][1]);
                const float e2 = __expf(acc[i][j][2]);
                const float e3 = __expf(acc[i][j][3]);
                slo += e0 + e1; shi += e2 + e3;
                *(uint32_t*)((bf16*)Cv + o0) = pk2(e0, e1);
                *(uint32_t*)((bf16*)Cv + o1) = pk2(e2, e3);
            } else {  // MODE 4
                const float2 r0 = *(const float2*)(R + o0);
                const float2 r1 = *(const float2*)(R + o1);
                *(float2*)((float*)Cv + o0) =
                    make_float2(acc[i][j][0] * il0 + r0.x, acc[i][j][1] * il0 + r0.y);
                *(float2*)((float*)Cv + o1) =
                    make_float2(acc[i][j][2] * il1 + r1.x, acc[i][j][3] * il1 + r1.y);
            }
        }
        if (MODE == 3) {
            slo += __shfl_xor_sync(0xFFFFFFFFu, slo, 1);
            slo += __shfl_xor_sync(0xFFFFFFFFu, slo, 2);
            shi += __shfl_xor_sync(0xFFFFFFFFu, shi, 1);
            shi += __shfl_xor_sync(0xFFFFFFFFu, shi, 2);
            if ((lane & 3) == 0) {
                atomicAdd(L + (long)bz * SEQ + row0, slo);
                atomicAdd(L + (long)bz * SEQ + rowb, shi);
            }
        }
    }
}

// ---------------- merged helper kernels --------------------------------------
// prep_all: z=0 -> cvt x (needs 4096 blocks), z=1 -> cvt ctx (6144 blocks),
//           z=2 -> zero L (64 blocks). Launch x-dim = 6144; excess blocks exit.
__global__ __launch_bounds__(256)
void prep_all(const float* __restrict__ x, const float* __restrict__ ctx,
              bf16* __restrict__ Xb, bf16* __restrict__ Cb,
              float* __restrict__ L)
{
    const int z = blockIdx.z;
    if (z == 2) {
        if (blockIdx.x < (BATCH * SEQ) / 256)
            L[blockIdx.x * 256 + threadIdx.x] = 0.0f;
        return;
    }
    const float* in = (z == 0) ? x : ctx;
    bf16* out = (z == 0) ? Xb : Cb;
    const long nvec = (z == 0) ? (long)BATCH * SEQ * DIM / 8
                               : (long)BATCH * SEQ * CTXD / 8;
    const long i = (long)blockIdx.x * 256 + threadIdx.x;
    if (i >= nvec) return;
    const float4* p = (const float4*)in + i * 2;
    const float4 a = p[0], b = p[1];
    ((uint4*)out)[i] = make_uint4(pk2(a.x, a.y), pk2(a.z, a.w),
                                  pk2(b.x, b.y), pk2(b.z, b.w));
}

// wtrans3: z=0 Wq(512x512), z=1 Wk(768x512), z=2 Wv(768x512); Nout=512 all.
__global__ __launch_bounds__(256)
void wtrans3(const float* __restrict__ Wq, const float* __restrict__ Wk,
             const float* __restrict__ Wv,
             bf16* __restrict__ WqT, bf16* __restrict__ WkT, bf16* __restrict__ WvT)
{
    const int z = blockIdx.z;
    const float* W = (z == 0) ? Wq : (z == 1) ? Wk : Wv;
    bf16* WT = (z == 0) ? WqT : (z == 1) ? WkT : WvT;
    const int Kin = (z == 0) ? DIM : CTXD;
    if (blockIdx.y * 32 >= Kin) return;

    __shared__ float t[32][33];
    const int n0 = blockIdx.x * 32, k0 = blockIdx.y * 32;
    const int tx = threadIdx.x & 31, ty = threadIdx.x >> 5;
#pragma unroll
    for (int i = 0; i < 4; i++)
        t[ty + 8 * i][tx] = W[(long)(k0 + ty + 8 * i) * DIM + n0 + tx];
    __syncthreads();
#pragma unroll
    for (int i = 0; i < 4; i++)
        WT[(long)(n0 + ty + 8 * i) * Kin + k0 + tx] = __float2bfloat16(t[tx][ty + 8 * i]);
}

__global__ __launch_bounds__(256)
void vtransb(const bf16* __restrict__ V, bf16* __restrict__ VT) {
    __shared__ bf16 t[32][33];
    const long boff = (long)blockIdx.z * SEQ * DIM;
    const int d0 = blockIdx.x * 32, m0 = blockIdx.y * 32;
    const int tx = threadIdx.x & 31, ty = threadIdx.x >> 5;
#pragma unroll
    for (int i = 0; i < 4; i++)
        t[ty + 8 * i][tx] = V[boff + (long)(m0 + ty + 8 * i) * DIM + d0 + tx];
    __syncthreads();
#pragma unroll
    for (int i = 0; i < 4; i++)
        VT[boff + (long)(d0 + ty + 8 * i) * SEQ + m0 + tx] = t[tx][ty + 8 * i];
}

// ---------------- launcher ---------------------------------------------------
extern "C" void kernel_launch(void* const* d_in, const int* in_sizes, int n_in,
                              void* d_out, int out_size)
{
    const float* x   = (const float*)d_in[0];
    const float* ctx = (const float*)d_in[1];
    const float* Wq  = (const float*)d_in[2];
    const float* Wk  = (const float*)d_in[3];
    const float* Wv  = (const float*)d_in[4];
    float* out = (float*)d_out;

    bf16 *Xb, *Cb, *WqT, *WkT, *WvT, *Qb, *Kb, *Vb, *VT, *P;
    float* L;
    cudaGetSymbolAddress((void**)&Xb,  g_Xb);
    cudaGetSymbolAddress((void**)&Cb,  g_Cb);
    cudaGetSymbolAddress((void**)&WqT, g_WqT);
    cudaGetSymbolAddress((void**)&WkT, g_WkT);
    cudaGetSymbolAddress((void**)&WvT, g_WvT);
    cudaGetSymbolAddress((void**)&Qb,  g_Qb);
    cudaGetSymbolAddress((void**)&Kb,  g_Kb);
    cudaGetSymbolAddress((void**)&Vb,  g_Vb);
    cudaGetSymbolAddress((void**)&VT,  g_VT);
    cudaGetSymbolAddress((void**)&P,   g_P);
    cudaGetSymbolAddress((void**)&L,   g_L);

    cudaFuncSetAttribute(gemm_mma<0>, cudaFuncAttributeMaxDynamicSharedMemorySize, GEMM_SMEM);
    cudaFuncSetAttribute(gemm_mma<3>, cudaFuncAttributeMaxDynamicSharedMemorySize, GEMM_SMEM);
    cudaFuncSetAttribute(gemm_mma<4>, cudaFuncAttributeMaxDynamicSharedMemorySize, GEMM_SMEM);

    const float scale = 0.044194173824159216f;  // 512^-0.5

    // merged prep: cvt x (4096 blocks), cvt ctx (6144), zero L (64)
    prep_all<<<dim3(6144, 1, 3), 256>>>(x, ctx, Xb, Cb, L);

    // merged weight transposes
    wtrans3<<<dim3(DIM / 32, CTXD / 32, 3), 256>>>(Wq, Wk, Wv, WqT, WkT, WvT);

    // projections (batch folded: 16384 rows). scale folded into Q.
    gemm_mma<0><<<dim3(DIM / 128, (BATCH * SEQ) / 256, 1), 256, GEMM_SMEM>>>(
        Xb, WqT, Qb, nullptr, nullptr, DIM, DIM, 0, 0, 0, scale);
    gemm_mma<0><<<dim3(DIM / 128, (BATCH * SEQ) / 256, 1), 256, GEMM_SMEM>>>(
        Cb, WkT, Kb, nullptr, nullptr, DIM, CTXD, 0, 0, 0, 1.0f);
    gemm_mma<0><<<dim3(DIM / 128, (BATCH * SEQ) / 256, 1), 256, GEMM_SMEM>>>(
        Cb, WvT, Vb, nullptr, nullptr, DIM, CTXD, 0, 0, 0, 1.0f);

    vtransb<<<dim3(DIM / 32, SEQ / 32, BATCH), 256>>>(Vb, VT);

    // P = exp(Q K^T), L = row sums (softmax fused into epilogue)
    gemm_mma<3><<<dim3(SEQ / 128, SEQ / 256, BATCH), 256, GEMM_SMEM>>>(
        Qb, Kb, P, nullptr, L, SEQ, DIM,
        (long)SEQ * DIM, (long)SEQ * DIM, (long)SEQ * SEQ, 1.0f);

    // out = (P V) / l + x
    gemm_mma<4><<<dim3(DIM / 128, SEQ / 256, BATCH), 256, GEMM_SMEM>>>(
        P, VT, out, x, L, DIM, SEQ,
        (long)SEQ * SEQ, (long)DIM * SEQ, (long)SEQ * DIM, 1.0f);
}

// round 14
// speedup vs baseline: 1.1187x; 1.0506x over previous
#include <cuda_runtime.h>
#include <cuda_bf16.h>
#include <cstdint>

// CrossAttention: out = softmax((x Wq)(ctx Wk)^T * DIM^-0.5) (ctx Wv) + x
// R13 pipeline with GEMM re-tiled for 2 CTAs/SM:
//   CTA 128x128, BK=64, 3-stage cp.async, 8 warps (2m x 4n), warp 64x32,
//   __launch_bounds__(256,2) caps regs at 128 -> two co-resident CTAs
//   overlap barrier stalls. Helpers merged (prep_all, wtrans3).

#define BATCH 4
#define SEQ   4096
#define DIM   512
#define CTXD  768

typedef __nv_bfloat16 bf16;

// ---------------- scratch ----------------------------------------------------
__device__ bf16  g_Xb [(size_t)BATCH * SEQ * DIM];
__device__ bf16  g_Cb [(size_t)BATCH * SEQ * CTXD];
__device__ bf16  g_WqT[(size_t)DIM * DIM];
__device__ bf16  g_WkT[(size_t)DIM * CTXD];
__device__ bf16  g_WvT[(size_t)DIM * CTXD];
__device__ bf16  g_Qb [(size_t)BATCH * SEQ * DIM];      // pre-scaled
__device__ bf16  g_Kb [(size_t)BATCH * SEQ * DIM];
__device__ bf16  g_Vb [(size_t)BATCH * SEQ * DIM];
__device__ bf16  g_VT [(size_t)BATCH * DIM * SEQ];
__device__ bf16  g_P  [(size_t)BATCH * SEQ * SEQ];      // exp(S)
__device__ float g_L  [(size_t)BATCH * SEQ];            // row sums

// ---------------- PTX helpers ------------------------------------------------
__device__ __forceinline__ uint32_t smem_u32(const void* p) {
    uint32_t a;
    asm("{ .reg .u64 t; cvta.to.shared.u64 t, %1; cvt.u32.u64 %0, t; }"
        : "=r"(a) : "l"(p));
    return a;
}
#define CP_ASYNC16(dst, src) \
    asm volatile("cp.async.cg.shared.global [%0], [%1], 16;" :: "r"(dst), "l"(src))
#define CP_COMMIT() asm volatile("cp.async.commit_group;" ::: "memory")
#define CP_WAIT(n)  asm volatile("cp.async.wait_group %0;" :: "n"(n) : "memory")

#define LDSM4(r0, r1, r2, r3, addr) \
    asm volatile("ldmatrix.sync.aligned.m8n8.x4.shared.b16 {%0,%1,%2,%3}, [%4];" \
        : "=r"(r0), "=r"(r1), "=r"(r2), "=r"(r3) : "r"(addr))

#define MMA16816(d, a, b) \
    asm volatile("mma.sync.aligned.m16n8k16.row.col.f32.bf16.bf16.f32 " \
        "{%0,%1,%2,%3}, {%4,%5,%6,%7}, {%8,%9}, {%0,%1,%2,%3};" \
        : "+f"((d)[0]), "+f"((d)[1]), "+f"((d)[2]), "+f"((d)[3]) \
        : "r"((a)[0]), "r"((a)[1]), "r"((a)[2]), "r"((a)[3]), \
          "r"((b)[0]), "r"((b)[1]))

__device__ __forceinline__ uint32_t pk2(float lo, float hi) {
    __nv_bfloat162 h = __floats2bfloat162_rn(lo, hi);
    return *reinterpret_cast<uint32_t*>(&h);
}

// ---------------- bf16 mma GEMM: D = A(M,K) * B(N,K)^T ----------------------
// CTA 128x128, BK=64, 3-stage cp.async, 8 warps 2x4, warp tile 64x32.
// MODE 0: bf16 out * alpha
// MODE 3: bf16 out = exp(acc); atomicAdd row-sums into L
// MODE 4: f32 out = acc / L[row] + residual R
#define STAGES 3
#define A_BYTES 16384                  // 128 x 64 bf16
#define B_BYTES 16384
#define STAGE_BYTES (A_BYTES + B_BYTES)
#define GEMM_SMEM (STAGES * STAGE_BYTES + 128)

__device__ __forceinline__ void tile_async(const bf16* g, int ld, uint32_t stg, int tid) {
#pragma unroll
    for (int t = 0; t < 4; t++) {
        const int f = tid + t * 256, row = f >> 3, seg = f & 7;
        CP_ASYNC16(stg + row * 128 + ((seg ^ (row & 7)) << 4),
                   (const char*)g + (long)row * ld * 2 + seg * 16);
    }
}

template <int MODE>
__global__ __launch_bounds__(256, 2)
void gemm_mma(const bf16* __restrict__ A, const bf16* __restrict__ B,
              void* __restrict__ Cv, const float* __restrict__ R,
              float* __restrict__ L,
              int Ncols, int Kd, long sA, long sB, long sC, float alpha)
{
    extern __shared__ char smraw[];
    const uint32_t smbase = (smem_u32(smraw) + 127u) & ~127u;

    const int tid = threadIdx.x, lane = tid & 31, wid = tid >> 5;
    const int wm = wid >> 2, wn = wid & 3;       // 2 x 4 warps, 64x32 tiles
    const int bz = blockIdx.z;
    const long bm = (long)blockIdx.y * 128;
    const long bn = (long)blockIdx.x * 128;

    A += bz * sA + bm * Kd;
    B += bz * sB + bn * Kd;

    const int g = lane >> 3, lr = lane & 7;
    const int arow0 = wm * 64 + (g & 1) * 8 + lr, aseg0 = g >> 1, axor = arow0 & 7;
    const int brow0 = wn * 32 + (g >> 1) * 8 + lr, bseg0 = g & 1, bxor = brow0 & 7;

    float acc[4][4][4];
#pragma unroll
    for (int i = 0; i < 4; i++)
#pragma unroll
        for (int j = 0; j < 4; j++)
#pragma unroll
            for (int q = 0; q < 4; q++) acc[i][j][q] = 0.0f;

    const int NC = Kd >> 6;
#pragma unroll
    for (int c = 0; c < 2; c++) {
        const uint32_t stg = smbase + c * STAGE_BYTES;
        tile_async(A + c * 64, Kd, stg, tid);
        tile_async(B + c * 64, Kd, stg + A_BYTES, tid);
        CP_COMMIT();
    }

    for (int c = 0; c < NC; c++) {
        if (c == NC - 1) { CP_WAIT(0); } else { CP_WAIT(1); }
        __syncthreads();
        if (c + 2 < NC) {
            const uint32_t stg = smbase + ((c + 2) % STAGES) * STAGE_BYTES;
            tile_async(A + (c + 2) * 64, Kd, stg, tid);
            tile_async(B + (c + 2) * 64, Kd, stg + A_BYTES, tid);
            CP_COMMIT();
        }
        const uint32_t sa = smbase + (c % STAGES) * STAGE_BYTES;
        const uint32_t sb = sa + A_BYTES;
#pragma unroll
        for (int ks = 0; ks < 4; ks++) {
            uint32_t af[4][4];
#pragma unroll
            for (int i = 0; i < 4; i++)
                LDSM4(af[i][0], af[i][1], af[i][2], af[i][3],
                      sa + (arow0 + i * 16) * 128 + ((((ks << 1) + aseg0) ^ axor) << 4));
            uint32_t bfr[4][2];
#pragma unroll
            for (int jp = 0; jp < 2; jp++) {
                uint32_t r0, r1, r2, r3;
                LDSM4(r0, r1, r2, r3,
                      sb + (brow0 + jp * 16) * 128 + ((((ks << 1) + bseg0) ^ bxor) << 4));
                bfr[2 * jp][0] = r0; bfr[2 * jp][1] = r1;
                bfr[2 * jp + 1][0] = r2; bfr[2 * jp + 1][1] = r3;
            }
#pragma unroll
            for (int i = 0; i < 4; i++)
#pragma unroll
                for (int j = 0; j < 4; j++)
                    MMA16816(acc[i][j], af[i], bfr[j]);
        }
    }

    // ---------------- epilogue ----------------
    const int r = lane >> 2, c2 = (lane & 3) * 2;
#pragma unroll
    for (int i = 0; i < 4; i++) {
        const long row0 = bm + wm * 64 + i * 16 + r;        // per-batch row
        const long rowb = row0 + 8;
        float il0 = 1.0f, il1 = 1.0f;
        if (MODE == 4) {
            il0 = 1.0f / __ldg(L + (long)bz * SEQ + row0);
            il1 = 1.0f / __ldg(L + (long)bz * SEQ + rowb);
        }
        float slo = 0.0f, shi = 0.0f;
#pragma unroll
        for (int j = 0; j < 4; j++) {
            const int  col = bn + wn * 32 + j * 8 + c2;
            const long o0 = row0 * (long)Ncols + col + bz * sC;
            const long o1 = rowb * (long)Ncols + col + bz * sC;
            if (MODE == 0) {
                *(uint32_t*)((bf16*)Cv + o0) = pk2(acc[i][j][0] * alpha, acc[i][j][1] * alpha);
                *(uint32_t*)((bf16*)Cv + o1) = pk2(acc[i][j][2] * alpha, acc[i][j][3] * alpha);
            } else if (MODE == 3) {
                const float e0 = __expf(acc[i][j][0]);
                const float e1 = __expf(acc[i][j][1]);
                const float e2 = __expf(acc[i][j][2]);
                const float e3 = __expf(acc[i][j][3]);
                slo += e0 + e1; shi += e2 + e3;
                *(uint32_t*)((bf16*)Cv + o0) = pk2(e0, e1);
                *(uint32_t*)((bf16*)Cv + o1) = pk2(e2, e3);
            } else {  // MODE 4
                const float2 r0 = *(const float2*)(R + o0);
                const float2 r1 = *(const float2*)(R + o1);
                *(float2*)((float*)Cv + o0) =
                    make_float2(acc[i][j][0] * il0 + r0.x, acc[i][j][1] * il0 + r0.y);
                *(float2*)((float*)Cv + o1) =
                    make_float2(acc[i][j][2] * il1 + r1.x, acc[i][j][3] * il1 + r1.y);
            }
        }
        if (MODE == 3) {
            slo += __shfl_xor_sync(0xFFFFFFFFu, slo, 1);
            slo += __shfl_xor_sync(0xFFFFFFFFu, slo, 2);
            shi += __shfl_xor_sync(0xFFFFFFFFu, shi, 1);
            shi += __shfl_xor_sync(0xFFFFFFFFu, shi, 2);
            if ((lane & 3) == 0) {
                atomicAdd(L + (long)bz * SEQ + row0, slo);
                atomicAdd(L + (long)bz * SEQ + rowb, shi);
            }
        }
    }
}

// ---------------- merged helper kernels --------------------------------------
// prep_all: z=0 -> cvt x (4096 blocks), z=1 -> cvt ctx (6144), z=2 -> zero L (64)
__global__ __launch_bounds__(256)
void prep_all(const float* __restrict__ x, const float* __restrict__ ctx,
              bf16* __restrict__ Xb, bf16* __restrict__ Cb,
              float* __restrict__ L)
{
    const int z = blockIdx.z;
    if (z == 2) {
        if (blockIdx.x < (BATCH * SEQ) / 256)
            L[blockIdx.x * 256 + threadIdx.x] = 0.0f;
        return;
    }
    const float* in = (z == 0) ? x : ctx;
    bf16* out = (z == 0) ? Xb : Cb;
    const long nvec = (z == 0) ? (long)BATCH * SEQ * DIM / 8
                               : (long)BATCH * SEQ * CTXD / 8;
    const long i = (long)blockIdx.x * 256 + threadIdx.x;
    if (i >= nvec) return;
    const float4* p = (const float4*)in + i * 2;
    const float4 a = p[0], b = p[1];
    ((uint4*)out)[i] = make_uint4(pk2(a.x, a.y), pk2(a.z, a.w),
                                  pk2(b.x, b.y), pk2(b.z, b.w));
}

// wtrans3: z=0 Wq(512x512), z=1 Wk(768x512), z=2 Wv(768x512); Nout=512 all.
__global__ __launch_bounds__(256)
void wtrans3(const float* __restrict__ Wq, const float* __restrict__ Wk,
             const float* __restrict__ Wv,
             bf16* __restrict__ WqT, bf16* __restrict__ WkT, bf16* __restrict__ WvT)
{
    const int z = blockIdx.z;
    const float* W = (z == 0) ? Wq : (z == 1) ? Wk : Wv;
    bf16* WT = (z == 0) ? WqT : (z == 1) ? WkT : WvT;
    const int Kin = (z == 0) ? DIM : CTXD;
    if (blockIdx.y * 32 >= Kin) return;

    __shared__ float t[32][33];
    const int n0 = blockIdx.x * 32, k0 = blockIdx.y * 32;
    const int tx = threadIdx.x & 31, ty = threadIdx.x >> 5;
#pragma unroll
    for (int i = 0; i < 4; i++)
        t[ty + 8 * i][tx] = W[(long)(k0 + ty + 8 * i) * DIM + n0 + tx];
    __syncthreads();
#pragma unroll
    for (int i = 0; i < 4; i++)
        WT[(long)(n0 + ty + 8 * i) * Kin + k0 + tx] = __float2bfloat16(t[tx][ty + 8 * i]);
}

__global__ __launch_bounds__(256)
void vtransb(const bf16* __restrict__ V, bf16* __restrict__ VT) {
    __shared__ bf16 t[32][33];
    const long boff = (long)blockIdx.z * SEQ * DIM;
    const int d0 = blockIdx.x * 32, m0 = blockIdx.y * 32;
    const int tx = threadIdx.x & 31, ty = threadIdx.x >> 5;
#pragma unroll
    for (int i = 0; i < 4; i++)
        t[ty + 8 * i][tx] = V[boff + (long)(m0 + ty + 8 * i) * DIM + d0 + tx];
    __syncthreads();
#pragma unroll
    for (int i = 0; i < 4; i++)
        VT[boff + (long)(d0 + ty + 8 * i) * SEQ + m0 + tx] = t[tx][ty + 8 * i];
}

// ---------------- launcher ---------------------------------------------------
extern "C" void kernel_launch(void* const* d_in, const int* in_sizes, int n_in,
                              void* d_out, int out_size)
{
    const float* x   = (const float*)d_in[0];
    const float* ctx = (const float*)d_in[1];
    const float* Wq  = (const float*)d_in[2];
    const float* Wk  = (const float*)d_in[3];
    const float* Wv  = (const float*)d_in[4];
    float* out = (float*)d_out;

    bf16 *Xb, *Cb, *WqT, *WkT, *WvT, *Qb, *Kb, *Vb, *VT, *P;
    float* L;
    cudaGetSymbolAddress((void**)&Xb,  g_Xb);
    cudaGetSymbolAddress((void**)&Cb,  g_Cb);
    cudaGetSymbolAddress((void**)&WqT, g_WqT);
    cudaGetSymbolAddress((void**)&WkT, g_WkT);
    cudaGetSymbolAddress((void**)&WvT, g_WvT);
    cudaGetSymbolAddress((void**)&Qb,  g_Qb);
    cudaGetSymbolAddress((void**)&Kb,  g_Kb);
    cudaGetSymbolAddress((void**)&Vb,  g_Vb);
    cudaGetSymbolAddress((void**)&VT,  g_VT);
    cudaGetSymbolAddress((void**)&P,   g_P);
    cudaGetSymbolAddress((void**)&L,   g_L);

    cudaFuncSetAttribute(gemm_mma<0>, cudaFuncAttributeMaxDynamicSharedMemorySize, GEMM_SMEM);
    cudaFuncSetAttribute(gemm_mma<3>, cudaFuncAttributeMaxDynamicSharedMemorySize, GEMM_SMEM);
    cudaFuncSetAttribute(gemm_mma<4>, cudaFuncAttributeMaxDynamicSharedMemorySize, GEMM_SMEM);

    const float scale = 0.044194173824159216f;  // 512^-0.5

    // merged prep: cvt x (4096 blocks), cvt ctx (6144), zero L (64)
    prep_all<<<dim3(6144, 1, 3), 256>>>(x, ctx, Xb, Cb, L);

    // merged weight transposes
    wtrans3<<<dim3(DIM / 32, CTXD / 32, 3), 256>>>(Wq, Wk, Wv, WqT, WkT, WvT);

    // projections (batch folded: 16384 rows). scale folded into Q.
    gemm_mma<0><<<dim3(DIM / 128, (BATCH * SEQ) / 128, 1), 256, GEMM_SMEM>>>(
        Xb, WqT, Qb, nullptr, nullptr, DIM, DIM, 0, 0, 0, scale);
    gemm_mma<0><<<dim3(DIM / 128, (BATCH * SEQ) / 128, 1), 256, GEMM_SMEM>>>(
        Cb, WkT, Kb, nullptr, nullptr, DIM, CTXD, 0, 0, 0, 1.0f);
    gemm_mma<0><<<dim3(DIM / 128, (BATCH * SEQ) / 128, 1), 256, GEMM_SMEM>>>(
        Cb, WvT, Vb, nullptr, nullptr, DIM, CTXD, 0, 0, 0, 1.0f);

    vtransb<<<dim3(DIM / 32, SEQ / 32, BATCH), 256>>>(Vb, VT);

    // P = exp(Q K^T), L = row sums (softmax fused into epilogue)
    gemm_mma<3><<<dim3(SEQ / 128, SEQ / 128, BATCH), 256, GEMM_SMEM>>>(
        Qb, Kb, P, nullptr, L, SEQ, DIM,
        (long)SEQ * DIM, (long)SEQ * DIM, (long)SEQ * SEQ, 1.0f);

    // out = (P V) / l + x
    gemm_mma<4><<<dim3(DIM / 128, SEQ / 128, BATCH), 256, GEMM_SMEM>>>(
        P, VT, out, x, L, DIM, SEQ,
        (long)SEQ * SEQ, (long)DIM * SEQ, (long)SEQ * DIM, 1.0f);
}

// round 15
// speedup vs baseline: 1.1551x; 1.0326x over previous
#include <cuda_runtime.h>
#include <cuda_bf16.h>
#include <cstdint>

// CrossAttention: out = softmax((x Wq)(ctx Wk)^T * DIM^-0.5) (ctx Wv) + x
// R14 pipeline, GEMM re-shaped: CTA 128x128 with 4 warps (128 thr, 2x2),
// warp tile 64x64 -> 8 LDSM : 32 MMA per k-step (33% less crossbar traffic
// per FLOP). No reg cap (no spills); smem 96KB/CTA -> 2 CTAs/SM.

#define BATCH 4
#define SEQ   4096
#define DIM   512
#define CTXD  768

typedef __nv_bfloat16 bf16;

// ---------------- scratch ----------------------------------------------------
__device__ bf16  g_Xb [(size_t)BATCH * SEQ * DIM];
__device__ bf16  g_Cb [(size_t)BATCH * SEQ * CTXD];
__device__ bf16  g_WqT[(size_t)DIM * DIM];
__device__ bf16  g_WkT[(size_t)DIM * CTXD];
__device__ bf16  g_WvT[(size_t)DIM * CTXD];
__device__ bf16  g_Qb [(size_t)BATCH * SEQ * DIM];      // pre-scaled
__device__ bf16  g_Kb [(size_t)BATCH * SEQ * DIM];
__device__ bf16  g_Vb [(size_t)BATCH * SEQ * DIM];
__device__ bf16  g_VT [(size_t)BATCH * DIM * SEQ];
__device__ bf16  g_P  [(size_t)BATCH * SEQ * SEQ];      // exp(S)
__device__ float g_L  [(size_t)BATCH * SEQ];            // row sums

// ---------------- PTX helpers ------------------------------------------------
__device__ __forceinline__ uint32_t smem_u32(const void* p) {
    uint32_t a;
    asm("{ .reg .u64 t; cvta.to.shared.u64 t, %1; cvt.u32.u64 %0, t; }"
        : "=r"(a) : "l"(p));
    return a;
}
#define CP_ASYNC16(dst, src) \
    asm volatile("cp.async.cg.shared.global [%0], [%1], 16;" :: "r"(dst), "l"(src))
#define CP_COMMIT() asm volatile("cp.async.commit_group;" ::: "memory")
#define CP_WAIT(n)  asm volatile("cp.async.wait_group %0;" :: "n"(n) : "memory")

#define LDSM4(r0, r1, r2, r3, addr) \
    asm volatile("ldmatrix.sync.aligned.m8n8.x4.shared.b16 {%0,%1,%2,%3}, [%4];" \
        : "=r"(r0), "=r"(r1), "=r"(r2), "=r"(r3) : "r"(addr))

#define MMA16816(d, a, b) \
    asm volatile("mma.sync.aligned.m16n8k16.row.col.f32.bf16.bf16.f32 " \
        "{%0,%1,%2,%3}, {%4,%5,%6,%7}, {%8,%9}, {%0,%1,%2,%3};" \
        : "+f"((d)[0]), "+f"((d)[1]), "+f"((d)[2]), "+f"((d)[3]) \
        : "r"((a)[0]), "r"((a)[1]), "r"((a)[2]), "r"((a)[3]), \
          "r"((b)[0]), "r"((b)[1]))

__device__ __forceinline__ uint32_t pk2(float lo, float hi) {
    __nv_bfloat162 h = __floats2bfloat162_rn(lo, hi);
    return *reinterpret_cast<uint32_t*>(&h);
}

// ---------------- bf16 mma GEMM: D = A(M,K) * B(N,K)^T ----------------------
// CTA 128x128, BK=64, 3-stage cp.async, 4 warps (2m x 2n), warp tile 64x64.
// MODE 0: bf16 out * alpha
// MODE 3: bf16 out = exp(acc); atomicAdd row-sums into L
// MODE 4: f32 out = acc / L[row] + residual R
#define NTHR 128
#define STAGES 3
#define A_BYTES 16384                  // 128 x 64 bf16
#define B_BYTES 16384
#define STAGE_BYTES (A_BYTES + B_BYTES)
#define GEMM_SMEM (STAGES * STAGE_BYTES + 128)

__device__ __forceinline__ void tile_async(const bf16* g, int ld, uint32_t stg, int tid) {
#pragma unroll
    for (int t = 0; t < 8; t++) {
        const int f = tid + t * NTHR, row = f >> 3, seg = f & 7;
        CP_ASYNC16(stg + row * 128 + ((seg ^ (row & 7)) << 4),
                   (const char*)g + (long)row * ld * 2 + seg * 16);
    }
}

template <int MODE>
__global__ __launch_bounds__(NTHR)
void gemm_mma(const bf16* __restrict__ A, const bf16* __restrict__ B,
              void* __restrict__ Cv, const float* __restrict__ R,
              float* __restrict__ L,
              int Ncols, int Kd, long sA, long sB, long sC, float alpha)
{
    extern __shared__ char smraw[];
    const uint32_t smbase = (smem_u32(smraw) + 127u) & ~127u;

    const int tid = threadIdx.x, lane = tid & 31, wid = tid >> 5;
    const int wm = wid >> 1, wn = wid & 1;       // 2 x 2 warps, 64x64 tiles
    const int bz = blockIdx.z;
    const long bm = (long)blockIdx.y * 128;
    const long bn = (long)blockIdx.x * 128;

    A += bz * sA + bm * Kd;
    B += bz * sB + bn * Kd;

    const int g = lane >> 3, lr = lane & 7;
    const int arow0 = wm * 64 + (g & 1) * 8 + lr, aseg0 = g >> 1, axor = arow0 & 7;
    const int brow0 = wn * 64 + (g >> 1) * 8 + lr, bseg0 = g & 1, bxor = brow0 & 7;

    float acc[4][8][4];
#pragma unroll
    for (int i = 0; i < 4; i++)
#pragma unroll
        for (int j = 0; j < 8; j++)
#pragma unroll
            for (int q = 0; q < 4; q++) acc[i][j][q] = 0.0f;

    const int NC = Kd >> 6;
#pragma unroll
    for (int c = 0; c < 2; c++) {
        const uint32_t stg = smbase + c * STAGE_BYTES;
        tile_async(A + c * 64, Kd, stg, tid);
        tile_async(B + c * 64, Kd, stg + A_BYTES, tid);
        CP_COMMIT();
    }

    for (int c = 0; c < NC; c++) {
        if (c == NC - 1) { CP_WAIT(0); } else { CP_WAIT(1); }
        __syncthreads();
        if (c + 2 < NC) {
            const uint32_t stg = smbase + ((c + 2) % STAGES) * STAGE_BYTES;
            tile_async(A + (c + 2) * 64, Kd, stg, tid);
            tile_async(B + (c + 2) * 64, Kd, stg + A_BYTES, tid);
            CP_COMMIT();
        }
        const uint32_t sa = smbase + (c % STAGES) * STAGE_BYTES;
        const uint32_t sb = sa + A_BYTES;
#pragma unroll
        for (int ks = 0; ks < 4; ks++) {
            uint32_t af[4][4];
#pragma unroll
            for (int i = 0; i < 4; i++)
                LDSM4(af[i][0], af[i][1], af[i][2], af[i][3],
                      sa + (arow0 + i * 16) * 128 + ((((ks << 1) + aseg0) ^ axor) << 4));
            uint32_t bfr[8][2];
#pragma unroll
            for (int jp = 0; jp < 4; jp++) {
                uint32_t r0, r1, r2, r3;
                LDSM4(r0, r1, r2, r3,
                      sb + (brow0 + jp * 16) * 128 + ((((ks << 1) + bseg0) ^ bxor) << 4));
                bfr[2 * jp][0] = r0; bfr[2 * jp][1] = r1;
                bfr[2 * jp + 1][0] = r2; bfr[2 * jp + 1][1] = r3;
            }
#pragma unroll
            for (int i = 0; i < 4; i++)
#pragma unroll
                for (int j = 0; j < 8; j++)
                    MMA16816(acc[i][j], af[i], bfr[j]);
        }
    }

    // ---------------- epilogue ----------------
    const int r = lane >> 2, c2 = (lane & 3) * 2;
#pragma unroll
    for (int i = 0; i < 4; i++) {
        const long row0 = bm + wm * 64 + i * 16 + r;        // per-batch row
        const long rowb = row0 + 8;
        float il0 = 1.0f, il1 = 1.0f;
        if (MODE == 4) {
            il0 = 1.0f / __ldg(L + (long)bz * SEQ + row0);
            il1 = 1.0f / __ldg(L + (long)bz * SEQ + rowb);
        }
        float slo = 0.0f, shi = 0.0f;
#pragma unroll
        for (int j = 0; j < 8; j++) {
            const int  col = bn + wn * 64 + j * 8 + c2;
            const long o0 = row0 * (long)Ncols + col + bz * sC;
            const long o1 = rowb * (long)Ncols + col + bz * sC;
            if (MODE == 0) {
                *(uint32_t*)((bf16*)Cv + o0) = pk2(acc[i][j][0] * alpha, acc[i][j][1] * alpha);
                *(uint32_t*)((bf16*)Cv + o1) = pk2(acc[i][j][2] * alpha, acc[i][j][3] * alpha);
            } else if (MODE == 3) {
                const float e0 = __expf(acc[i][j][0]);
                const float e1 = __expf(acc[i][j][1]);
                const float e2 = __expf(acc[i][j][2]);
                const float e3 = __expf(acc[i][j][3]);
                slo += e0 + e1; shi += e2 + e3;
                *(uint32_t*)((bf16*)Cv + o0) = pk2(e0, e1);
                *(uint32_t*)((bf16*)Cv + o1) = pk2(e2, e3);
            } else {  // MODE 4
                const float2 r0 = *(const float2*)(R + o0);
                const float2 r1 = *(const float2*)(R + o1);
                *(float2*)((float*)Cv + o0) =
                    make_float2(acc[i][j][0] * il0 + r0.x, acc[i][j][1] * il0 + r0.y);
                *(float2*)((float*)Cv + o1) =
                    make_float2(acc[i][j][2] * il1 + r1.x, acc[i][j][3] * il1 + r1.y);
            }
        }
        if (MODE == 3) {
            slo += __shfl_xor_sync(0xFFFFFFFFu, slo, 1);
            slo += __shfl_xor_sync(0xFFFFFFFFu, slo, 2);
            shi += __shfl_xor_sync(0xFFFFFFFFu, shi, 1);
            shi += __shfl_xor_sync(0xFFFFFFFFu, shi, 2);
            if ((lane & 3) == 0) {
                atomicAdd(L + (long)bz * SEQ + row0, slo);
                atomicAdd(L + (long)bz * SEQ + rowb, shi);
            }
        }
    }
}

// ---------------- merged helper kernels --------------------------------------
// prep_all: z=0 -> cvt x (4096 blocks), z=1 -> cvt ctx (6144), z=2 -> zero L (64)
__global__ __launch_bounds__(256)
void prep_all(const float* __restrict__ x, const float* __restrict__ ctx,
              bf16* __restrict__ Xb, bf16* __restrict__ Cb,
              float* __restrict__ L)
{
    const int z = blockIdx.z;
    if (z == 2) {
        if (blockIdx.x < (BATCH * SEQ) / 256)
            L[blockIdx.x * 256 + threadIdx.x] = 0.0f;
        return;
    }
    const float* in = (z == 0) ? x : ctx;
    bf16* out = (z == 0) ? Xb : Cb;
    const long nvec = (z == 0) ? (long)BATCH * SEQ * DIM / 8
                               : (long)BATCH * SEQ * CTXD / 8;
    const long i = (long)blockIdx.x * 256 + threadIdx.x;
    if (i >= nvec) return;
    const float4* p = (const float4*)in + i * 2;
    const float4 a = p[0], b = p[1];
    ((uint4*)out)[i] = make_uint4(pk2(a.x, a.y), pk2(a.z, a.w),
                                  pk2(b.x, b.y), pk2(b.z, b.w));
}

// wtrans3: z=0 Wq(512x512), z=1 Wk(768x512), z=2 Wv(768x512); Nout=512 all.
__global__ __launch_bounds__(256)
void wtrans3(const float* __restrict__ Wq, const float* __restrict__ Wk,
             const float* __restrict__ Wv,
             bf16* __restrict__ WqT, bf16* __restrict__ WkT, bf16* __restrict__ WvT)
{
    const int z = blockIdx.z;
    const float* W = (z == 0) ? Wq : (z == 1) ? Wk : Wv;
    bf16* WT = (z == 0) ? WqT : (z == 1) ? WkT : WvT;
    const int Kin = (z == 0) ? DIM : CTXD;
    if (blockIdx.y * 32 >= Kin) return;

    __shared__ float t[32][33];
    const int n0 = blockIdx.x * 32, k0 = blockIdx.y * 32;
    const int tx = threadIdx.x & 31, ty = threadIdx.x >> 5;
#pragma unroll
    for (int i = 0; i < 4; i++)
        t[ty + 8 * i][tx] = W[(long)(k0 + ty + 8 * i) * DIM + n0 + tx];
    __syncthreads();
#pragma unroll
    for (int i = 0; i < 4; i++)
        WT[(long)(n0 + ty + 8 * i) * Kin + k0 + tx] = __float2bfloat16(t[tx][ty + 8 * i]);
}

__global__ __launch_bounds__(256)
void vtransb(const bf16* __restrict__ V, bf16* __restrict__ VT) {
    __shared__ bf16 t[32][33];
    const long boff = (long)blockIdx.z * SEQ * DIM;
    const int d0 = blockIdx.x * 32, m0 = blockIdx.y * 32;
    const int tx = threadIdx.x & 31, ty = threadIdx.x >> 5;
#pragma unroll
    for (int i = 0; i < 4; i++)
        t[ty + 8 * i][tx] = V[boff + (long)(m0 + ty + 8 * i) * DIM + d0 + tx];
    __syncthreads();
#pragma unroll
    for (int i = 0; i < 4; i++)
        VT[boff + (long)(d0 + ty + 8 * i) * SEQ + m0 + tx] = t[tx][ty + 8 * i];
}

// ---------------- launcher ---------------------------------------------------
extern "C" void kernel_launch(void* const* d_in, const int* in_sizes, int n_in,
                              void* d_out, int out_size)
{
    const float* x   = (const float*)d_in[0];
    const float* ctx = (const float*)d_in[1];
    const float* Wq  = (const float*)d_in[2];
    const float* Wk  = (const float*)d_in[3];
    const float* Wv  = (const float*)d_in[4];
    float* out = (float*)d_out;

    bf16 *Xb, *Cb, *WqT, *WkT, *WvT, *Qb, *Kb, *Vb, *VT, *P;
    float* L;
    cudaGetSymbolAddress((void**)&Xb,  g_Xb);
    cudaGetSymbolAddress((void**)&Cb,  g_Cb);
    cudaGetSymbolAddress((void**)&WqT, g_WqT);
    cudaGetSymbolAddress((void**)&WkT, g_WkT);
    cudaGetSymbolAddress((void**)&WvT, g_WvT);
    cudaGetSymbolAddress((void**)&Qb,  g_Qb);
    cudaGetSymbolAddress((void**)&Kb,  g_Kb);
    cudaGetSymbolAddress((void**)&Vb,  g_Vb);
    cudaGetSymbolAddress((void**)&VT,  g_VT);
    cudaGetSymbolAddress((void**)&P,   g_P);
    cudaGetSymbolAddress((void**)&L,   g_L);

    cudaFuncSetAttribute(gemm_mma<0>, cudaFuncAttributeMaxDynamicSharedMemorySize, GEMM_SMEM);
    cudaFuncSetAttribute(gemm_mma<3>, cudaFuncAttributeMaxDynamicSharedMemorySize, GEMM_SMEM);
    cudaFuncSetAttribute(gemm_mma<4>, cudaFuncAttributeMaxDynamicSharedMemorySize, GEMM_SMEM);

    const float scale = 0.044194173824159216f;  // 512^-0.5

    // merged prep: cvt x (4096 blocks), cvt ctx (6144), zero L (64)
    prep_all<<<dim3(6144, 1, 3), 256>>>(x, ctx, Xb, Cb, L);

    // merged weight transposes
    wtrans3<<<dim3(DIM / 32, CTXD / 32, 3), 256>>>(Wq, Wk, Wv, WqT, WkT, WvT);

    // projections (batch folded: 16384 rows). scale folded into Q.
    gemm_mma<0><<<dim3(DIM / 128, (BATCH * SEQ) / 128, 1), NTHR, GEMM_SMEM>>>(
        Xb, WqT, Qb, nullptr, nullptr, DIM, DIM, 0, 0, 0, scale);
    gemm_mma<0><<<dim3(DIM / 128, (BATCH * SEQ) / 128, 1), NTHR, GEMM_SMEM>>>(
        Cb, WkT, Kb, nullptr, nullptr, DIM, CTXD, 0, 0, 0, 1.0f);
    gemm_mma<0><<<dim3(DIM / 128, (BATCH * SEQ) / 128, 1), NTHR, GEMM_SMEM>>>(
        Cb, WvT, Vb, nullptr, nullptr, DIM, CTXD, 0, 0, 0, 1.0f);

    vtransb<<<dim3(DIM / 32, SEQ / 32, BATCH), 256>>>(Vb, VT);

    // P = exp(Q K^T), L = row sums (softmax fused into epilogue)
    gemm_mma<3><<<dim3(SEQ / 128, SEQ / 128, BATCH), NTHR, GEMM_SMEM>>>(
        Qb, Kb, P, nullptr, L, SEQ, DIM,
        (long)SEQ * DIM, (long)SEQ * DIM, (long)SEQ * SEQ, 1.0f);

    // out = (P V) / l + x
    gemm_mma<4><<<dim3(DIM / 128, SEQ / 128, BATCH), NTHR, GEMM_SMEM>>>(
        P, VT, out, x, L, DIM, SEQ,
        (long)SEQ * SEQ, (long)DIM * SEQ, (long)SEQ * DIM, 1.0f);
}

// round 16
// speedup vs baseline: 1.1826x; 1.0238x over previous
#include <cuda_runtime.h>
#include <cuda_bf16.h>
#include <cstdint>

// CrossAttention: out = softmax((x Wq)(ctx Wk)^T * DIM^-0.5) (ctx Wv) + x
// R15 pipeline (551us) + merged projection launch:
//   prep_all ; wtrans3 ; proj3 (Q|K|V in one grid, z-dispatch) ; V^T ;
//   S GEMM + exp epilogue + row-sum atomics ; PV GEMM with 1/l + residual.
// GEMM: CTA 128x128, BK=64, 3-stage cp.async, 4 warps (2x2), warp 64x64.

#define BATCH 4
#define SEQ   4096
#define DIM   512
#define CTXD  768

typedef __nv_bfloat16 bf16;

// ---------------- scratch ----------------------------------------------------
__device__ bf16  g_Xb [(size_t)BATCH * SEQ * DIM];
__device__ bf16  g_Cb [(size_t)BATCH * SEQ * CTXD];
__device__ bf16  g_WqT[(size_t)DIM * DIM];
__device__ bf16  g_WkT[(size_t)DIM * CTXD];
__device__ bf16  g_WvT[(size_t)DIM * CTXD];
__device__ bf16  g_Qb [(size_t)BATCH * SEQ * DIM];      // pre-scaled
__device__ bf16  g_Kb [(size_t)BATCH * SEQ * DIM];
__device__ bf16  g_Vb [(size_t)BATCH * SEQ * DIM];
__device__ bf16  g_VT [(size_t)BATCH * DIM * SEQ];
__device__ bf16  g_P  [(size_t)BATCH * SEQ * SEQ];      // exp(S)
__device__ float g_L  [(size_t)BATCH * SEQ];            // row sums

// ---------------- PTX helpers ------------------------------------------------
__device__ __forceinline__ uint32_t smem_u32(const void* p) {
    uint32_t a;
    asm("{ .reg .u64 t; cvta.to.shared.u64 t, %1; cvt.u32.u64 %0, t; }"
        : "=r"(a) : "l"(p));
    return a;
}
#define CP_ASYNC16(dst, src) \
    asm volatile("cp.async.cg.shared.global [%0], [%1], 16;" :: "r"(dst), "l"(src))
#define CP_COMMIT() asm volatile("cp.async.commit_group;" ::: "memory")
#define CP_WAIT(n)  asm volatile("cp.async.wait_group %0;" :: "n"(n) : "memory")

#define LDSM4(r0, r1, r2, r3, addr) \
    asm volatile("ldmatrix.sync.aligned.m8n8.x4.shared.b16 {%0,%1,%2,%3}, [%4];" \
        : "=r"(r0), "=r"(r1), "=r"(r2), "=r"(r3) : "r"(addr))

#define MMA16816(d, a, b) \
    asm volatile("mma.sync.aligned.m16n8k16.row.col.f32.bf16.bf16.f32 " \
        "{%0,%1,%2,%3}, {%4,%5,%6,%7}, {%8,%9}, {%0,%1,%2,%3};" \
        : "+f"((d)[0]), "+f"((d)[1]), "+f"((d)[2]), "+f"((d)[3]) \
        : "r"((a)[0]), "r"((a)[1]), "r"((a)[2]), "r"((a)[3]), \
          "r"((b)[0]), "r"((b)[1]))

__device__ __forceinline__ uint32_t pk2(float lo, float hi) {
    __nv_bfloat162 h = __floats2bfloat162_rn(lo, hi);
    return *reinterpret_cast<uint32_t*>(&h);
}

// ---------------- shared GEMM body: D = A(128,K) * B(128,K)^T ---------------
// A/B pre-offset to tile start. 4 warps (2m x 2n), warp tile 64x64, BK=64,
// 3-stage cp.async. Epilogue by MODE (0: bf16*alpha, 3: exp+Lsum, 4: /L + R).
#define NTHR 128
#define STAGES 3
#define A_BYTES 16384
#define B_BYTES 16384
#define STAGE_BYTES (A_BYTES + B_BYTES)
#define GEMM_SMEM (STAGES * STAGE_BYTES + 128)

__device__ __forceinline__ void tile_async(const bf16* g, int ld, uint32_t stg, int tid) {
#pragma unroll
    for (int t = 0; t < 8; t++) {
        const int f = tid + t * NTHR, row = f >> 3, seg = f & 7;
        CP_ASYNC16(stg + row * 128 + ((seg ^ (row & 7)) << 4),
                   (const char*)g + (long)row * ld * 2 + seg * 16);
    }
}

template <int MODE>
__device__ __forceinline__ void gemm_body(
    const bf16* __restrict__ A, const bf16* __restrict__ B,
    void* __restrict__ Cv, const float* __restrict__ R,
    float* __restrict__ L,                 // pre-offset by batch
    int Ncols, int Kd, long bm, long bn, long cOff, float alpha, char* smraw)
{
    const uint32_t smbase = (smem_u32(smraw) + 127u) & ~127u;
    const int tid = threadIdx.x, lane = tid & 31, wid = tid >> 5;
    const int wm = wid >> 1, wn = wid & 1;

    const int g = lane >> 3, lr = lane & 7;
    const int arow0 = wm * 64 + (g & 1) * 8 + lr, aseg0 = g >> 1, axor = arow0 & 7;
    const int brow0 = wn * 64 + (g >> 1) * 8 + lr, bseg0 = g & 1, bxor = brow0 & 7;

    float acc[4][8][4];
#pragma unroll
    for (int i = 0; i < 4; i++)
#pragma unroll
        for (int j = 0; j < 8; j++)
#pragma unroll
            for (int q = 0; q < 4; q++) acc[i][j][q] = 0.0f;

    const int NC = Kd >> 6;
#pragma unroll
    for (int c = 0; c < 2; c++) {
        const uint32_t stg = smbase + c * STAGE_BYTES;
        tile_async(A + c * 64, Kd, stg, tid);
        tile_async(B + c * 64, Kd, stg + A_BYTES, tid);
        CP_COMMIT();
    }

    for (int c = 0; c < NC; c++) {
        if (c == NC - 1) { CP_WAIT(0); } else { CP_WAIT(1); }
        __syncthreads();
        if (c + 2 < NC) {
            const uint32_t stg = smbase + ((c + 2) % STAGES) * STAGE_BYTES;
            tile_async(A + (c + 2) * 64, Kd, stg, tid);
            tile_async(B + (c + 2) * 64, Kd, stg + A_BYTES, tid);
            CP_COMMIT();
        }
        const uint32_t sa = smbase + (c % STAGES) * STAGE_BYTES;
        const uint32_t sb = sa + A_BYTES;
#pragma unroll
        for (int ks = 0; ks < 4; ks++) {
            uint32_t af[4][4];
#pragma unroll
            for (int i = 0; i < 4; i++)
                LDSM4(af[i][0], af[i][1], af[i][2], af[i][3],
                      sa + (arow0 + i * 16) * 128 + ((((ks << 1) + aseg0) ^ axor) << 4));
            uint32_t bfr[8][2];
#pragma unroll
            for (int jp = 0; jp < 4; jp++) {
                uint32_t r0, r1, r2, r3;
                LDSM4(r0, r1, r2, r3,
                      sb + (brow0 + jp * 16) * 128 + ((((ks << 1) + bseg0) ^ bxor) << 4));
                bfr[2 * jp][0] = r0; bfr[2 * jp][1] = r1;
                bfr[2 * jp + 1][0] = r2; bfr[2 * jp + 1][1] = r3;
            }
#pragma unroll
            for (int i = 0; i < 4; i++)
#pragma unroll
                for (int j = 0; j < 8; j++)
                    MMA16816(acc[i][j], af[i], bfr[j]);
        }
    }

    // ---------------- epilogue ----------------
    const int r = lane >> 2, c2 = (lane & 3) * 2;
#pragma unroll
    for (int i = 0; i < 4; i++) {
        const long row0 = bm + wm * 64 + i * 16 + r;
        const long rowb = row0 + 8;
        float il0 = 1.0f, il1 = 1.0f;
        if (MODE == 4) {
            il0 = 1.0f / __ldg(L + row0);
            il1 = 1.0f / __ldg(L + rowb);
        }
        float slo = 0.0f, shi = 0.0f;
#pragma unroll
        for (int j = 0; j < 8; j++) {
            const int  col = bn + wn * 64 + j * 8 + c2;
            const long o0 = row0 * (long)Ncols + col + cOff;
            const long o1 = rowb * (long)Ncols + col + cOff;
            if (MODE == 0) {
                *(uint32_t*)((bf16*)Cv + o0) = pk2(acc[i][j][0] * alpha, acc[i][j][1] * alpha);
                *(uint32_t*)((bf16*)Cv + o1) = pk2(acc[i][j][2] * alpha, acc[i][j][3] * alpha);
            } else if (MODE == 3) {
                const float e0 = __expf(acc[i][j][0]);
                const float e1 = __expf(acc[i][j][1]);
                const float e2 = __expf(acc[i][j][2]);
                const float e3 = __expf(acc[i][j][3]);
                slo += e0 + e1; shi += e2 + e3;
                *(uint32_t*)((bf16*)Cv + o0) = pk2(e0, e1);
                *(uint32_t*)((bf16*)Cv + o1) = pk2(e2, e3);
            } else {  // MODE 4
                const float2 r0 = *(const float2*)(R + o0);
                const float2 r1 = *(const float2*)(R + o1);
                *(float2*)((float*)Cv + o0) =
                    make_float2(acc[i][j][0] * il0 + r0.x, acc[i][j][1] * il0 + r0.y);
                *(float2*)((float*)Cv + o1) =
                    make_float2(acc[i][j][2] * il1 + r1.x, acc[i][j][3] * il1 + r1.y);
            }
        }
        if (MODE == 3) {
            slo += __shfl_xor_sync(0xFFFFFFFFu, slo, 1);
            slo += __shfl_xor_sync(0xFFFFFFFFu, slo, 2);
            shi += __shfl_xor_sync(0xFFFFFFFFu, shi, 1);
            shi += __shfl_xor_sync(0xFFFFFFFFu, shi, 2);
            if ((lane & 3) == 0) {
                atomicAdd(L + row0, slo);
                atomicAdd(L + rowb, shi);
            }
        }
    }
}

// ---------------- kernels -----------------------------------------------------
// merged projections: z=0 Q = Xb WqT * scale (K=512); z=1 K = Cb WkT (K=768);
// z=2 V = Cb WvT (K=768). grid = (4, 128, 3).
__global__ __launch_bounds__(NTHR)
void proj3(const bf16* __restrict__ Xb, const bf16* __restrict__ Cb,
           const bf16* __restrict__ WqT, const bf16* __restrict__ WkT,
           const bf16* __restrict__ WvT,
           bf16* __restrict__ Qb, bf16* __restrict__ Kb, bf16* __restrict__ Vb,
           float scale)
{
    extern __shared__ char smraw[];
    const int z = blockIdx.z;
    const bf16* A = (z == 0) ? Xb  : Cb;
    const bf16* B = (z == 0) ? WqT : (z == 1) ? WkT : WvT;
    bf16* C      = (z == 0) ? Qb  : (z == 1) ? Kb  : Vb;
    const int Kd = (z == 0) ? DIM : CTXD;
    const float a = (z == 0) ? scale : 1.0f;
    const long bm = (long)blockIdx.y * 128;
    const long bn = (long)blockIdx.x * 128;
    gemm_body<0>(A + bm * Kd, B + bn * Kd, C, nullptr, nullptr,
                 DIM, Kd, bm, bn, 0, a, smraw);
}

template <int MODE>
__global__ __launch_bounds__(NTHR)
void gemm_mma(const bf16* __restrict__ A, const bf16* __restrict__ B,
              void* __restrict__ Cv, const float* __restrict__ R,
              float* __restrict__ L,
              int Ncols, int Kd, long sA, long sB, long sC, float alpha)
{
    extern __shared__ char smraw[];
    const int bz = blockIdx.z;
    const long bm = (long)blockIdx.y * 128;
    const long bn = (long)blockIdx.x * 128;
    gemm_body<MODE>(A + bz * sA + bm * Kd, B + bz * sB + bn * Kd, Cv, R,
                    L ? (L + (long)bz * SEQ) : nullptr,
                    Ncols, Kd, bm, bn, (long)bz * sC, alpha, smraw);
}

// ---------------- merged helper kernels --------------------------------------
__global__ __launch_bounds__(256)
void prep_all(const float* __restrict__ x, const float* __restrict__ ctx,
              bf16* __restrict__ Xb, bf16* __restrict__ Cb,
              float* __restrict__ L)
{
    const int z = blockIdx.z;
    if (z == 2) {
        if (blockIdx.x < (BATCH * SEQ) / 256)
            L[blockIdx.x * 256 + threadIdx.x] = 0.0f;
        return;
    }
    const float* in = (z == 0) ? x : ctx;
    bf16* out = (z == 0) ? Xb : Cb;
    const long nvec = (z == 0) ? (long)BATCH * SEQ * DIM / 8
                               : (long)BATCH * SEQ * CTXD / 8;
    const long i = (long)blockIdx.x * 256 + threadIdx.x;
    if (i >= nvec) return;
    const float4* p = (const float4*)in + i * 2;
    const float4 a = p[0], b = p[1];
    ((uint4*)out)[i] = make_uint4(pk2(a.x, a.y), pk2(a.z, a.w),
                                  pk2(b.x, b.y), pk2(b.z, b.w));
}

__global__ __launch_bounds__(256)
void wtrans3(const float* __restrict__ Wq, const float* __restrict__ Wk,
             const float* __restrict__ Wv,
             bf16* __restrict__ WqT, bf16* __restrict__ WkT, bf16* __restrict__ WvT)
{
    const int z = blockIdx.z;
    const float* W = (z == 0) ? Wq : (z == 1) ? Wk : Wv;
    bf16* WT = (z == 0) ? WqT : (z == 1) ? WkT : WvT;
    const int Kin = (z == 0) ? DIM : CTXD;
    if (blockIdx.y * 32 >= Kin) return;

    __shared__ float t[32][33];
    const int n0 = blockIdx.x * 32, k0 = blockIdx.y * 32;
    const int tx = threadIdx.x & 31, ty = threadIdx.x >> 5;
#pragma unroll
    for (int i = 0; i < 4; i++)
        t[ty + 8 * i][tx] = W[(long)(k0 + ty + 8 * i) * DIM + n0 + tx];
    __syncthreads();
#pragma unroll
    for (int i = 0; i < 4; i++)
        WT[(long)(n0 + ty + 8 * i) * Kin + k0 + tx] = __float2bfloat16(t[tx][ty + 8 * i]);
}

__global__ __launch_bounds__(256)
void vtransb(const bf16* __restrict__ V, bf16* __restrict__ VT) {
    __shared__ bf16 t[32][33];
    const long boff = (long)blockIdx.z * SEQ * DIM;
    const int d0 = blockIdx.x * 32, m0 = blockIdx.y * 32;
    const int tx = threadIdx.x & 31, ty = threadIdx.x >> 5;
#pragma unroll
    for (int i = 0; i < 4; i++)
        t[ty + 8 * i][tx] = V[boff + (long)(m0 + ty + 8 * i) * DIM + d0 + tx];
    __syncthreads();
#pragma unroll
    for (int i = 0; i < 4; i++)
        VT[boff + (long)(d0 + ty + 8 * i) * SEQ + m0 + tx] = t[tx][ty + 8 * i];
}

// ---------------- launcher ---------------------------------------------------
extern "C" void kernel_launch(void* const* d_in, const int* in_sizes, int n_in,
                              void* d_out, int out_size)
{
    const float* x   = (const float*)d_in[0];
    const float* ctx = (const float*)d_in[1];
    const float* Wq  = (const float*)d_in[2];
    const float* Wk  = (const float*)d_in[3];
    const float* Wv  = (const float*)d_in[4];
    float* out = (float*)d_out;

    bf16 *Xb, *Cb, *WqT, *WkT, *WvT, *Qb, *Kb, *Vb, *VT, *P;
    float* L;
    cudaGetSymbolAddress((void**)&Xb,  g_Xb);
    cudaGetSymbolAddress((void**)&Cb,  g_Cb);
    cudaGetSymbolAddress((void**)&WqT, g_WqT);
    cudaGetSymbolAddress((void**)&WkT, g_WkT);
    cudaGetSymbolAddress((void**)&WvT, g_WvT);
    cudaGetSymbolAddress((void**)&Qb,  g_Qb);
    cudaGetSymbolAddress((void**)&Kb,  g_Kb);
    cudaGetSymbolAddress((void**)&Vb,  g_Vb);
    cudaGetSymbolAddress((void**)&VT,  g_VT);
    cudaGetSymbolAddress((void**)&P,   g_P);
    cudaGetSymbolAddress((void**)&L,   g_L);

    cudaFuncSetAttribute(proj3,       cudaFuncAttributeMaxDynamicSharedMemorySize, GEMM_SMEM);
    cudaFuncSetAttribute(gemm_mma<3>, cudaFuncAttributeMaxDynamicSharedMemorySize, GEMM_SMEM);
    cudaFuncSetAttribute(gemm_mma<4>, cudaFuncAttributeMaxDynamicSharedMemorySize, GEMM_SMEM);

    const float scale = 0.044194173824159216f;  // 512^-0.5

    // merged prep: cvt x (4096 blocks), cvt ctx (6144), zero L (64)
    prep_all<<<dim3(6144, 1, 3), 256>>>(x, ctx, Xb, Cb, L);

    // merged weight transposes
    wtrans3<<<dim3(DIM / 32, CTXD / 32, 3), 256>>>(Wq, Wk, Wv, WqT, WkT, WvT);

    // merged projections: Q | K | V in one launch (z-dispatch)
    proj3<<<dim3(DIM / 128, (BATCH * SEQ) / 128, 3), NTHR, GEMM_SMEM>>>(
        Xb, Cb, WqT, WkT, WvT, Qb, Kb, Vb, scale);

    vtransb<<<dim3(DIM / 32, SEQ / 32, BATCH), 256>>>(Vb, VT);

    // P = exp(Q K^T), L = row sums (softmax fused into epilogue)
    gemm_mma<3><<<dim3(SEQ / 128, SEQ / 128, BATCH), NTHR, GEMM_SMEM>>>(
        Qb, Kb, P, nullptr, L, SEQ, DIM,
        (long)SEQ * DIM, (long)SEQ * DIM, (long)SEQ * SEQ, 1.0f);

    // out = (P V) / l + x
    gemm_mma<4><<<dim3(DIM / 128, SEQ / 128, BATCH), NTHR, GEMM_SMEM>>>(
        P, VT, out, x, L, DIM, SEQ,
        (long)SEQ * SEQ, (long)DIM * SEQ, (long)SEQ * DIM, 1.0f);
}